// round 15
// baseline (speedup 1.0000x reference)
#include <cuda_runtime.h>
#include <cuda_fp16.h>
#include <math.h>

#define NB 2
#define NS 2048
#define NH 16
#define HD 64
#define NDIM 1024
#define NM (NB*NS)
#define OUT_ELEMS (NB*NS*NDIM)   // 4194304 per tensor (out, k, v)

// Scratch (allocation-free rule: __device__ globals)
__device__ __align__(256) __half g_ah[NM*NDIM];       // ctx half (A of out-proj)
__device__ __align__(256) __half g_inh[3*NM*NDIM];    // half query/key/value inputs
__device__ __align__(256) __half g_wh[4*NDIM*NDIM];   // half Wq/Wk/Wv/Wo
__device__ __align__(256) __half g_qh[NB*NH*NS*HD];   // half Q (post-RoPE, pre-scaled)
__device__ __align__(256) __half g_kh[NB*NH*NS*HD];   // half K (post-RoPE)
__device__ __align__(256) __half g_vTh[NB*NH*HD*NS];  // half V transposed [b,h,d,s]
__device__ __align__(256) unsigned g_mb[NB*NS*64];    // mask bitwords
__device__ float g_cos[NS*32];
__device__ float g_sin[NS*32];

#define SCALE2 0.18033688011112042f   // 0.125 * log2(e)

__device__ __forceinline__ unsigned packh2(float x, float y) {
    __half2 h = __floats2half2_rn(x, y);
    return *(unsigned*)&h;
}
__device__ __forceinline__ float fex2(float x) {
    float r; asm("ex2.approx.ftz.f32 %0, %1;" : "=f"(r) : "f"(x)); return r;
}
__device__ __forceinline__ void mma_f16(float c[4], unsigned a0, unsigned a1,
                                        unsigned a2, unsigned a3,
                                        unsigned b0, unsigned b1) {
    asm volatile(
        "mma.sync.aligned.m16n8k16.row.col.f32.f16.f16.f32 "
        "{%0,%1,%2,%3}, {%4,%5,%6,%7}, {%8,%9}, {%0,%1,%2,%3};"
        : "+f"(c[0]), "+f"(c[1]), "+f"(c[2]), "+f"(c[3])
        : "r"(a0), "r"(a1), "r"(a2), "r"(a3), "r"(b0), "r"(b1));
}
__device__ __forceinline__ void ldsm4(unsigned &r0, unsigned &r1, unsigned &r2,
                                      unsigned &r3, const void* p) {
    unsigned a = (unsigned)__cvta_generic_to_shared(p);
    asm volatile("ldmatrix.sync.aligned.m8n8.x4.shared.b16 {%0,%1,%2,%3}, [%4];"
                 : "=r"(r0), "=r"(r1), "=r"(r2), "=r"(r3) : "r"(a));
}
#define CP16(dst_u32, src_ptr) \
    asm volatile("cp.async.ca.shared.global [%0], [%1], 16;" \
                 :: "r"(dst_u32), "l"(src_ptr))
#define CP_COMMIT() asm volatile("cp.async.commit_group;" ::: "memory")
#define CP_WAIT1()  asm volatile("cp.async.wait_group 1;" ::: "memory")
#define CP_WAIT2()  asm volatile("cp.async.wait_group 2;" ::: "memory")

// ---------------------------------------------------------------------------
// RoPE tables
// ---------------------------------------------------------------------------
__global__ void rope_table_kernel() {
    int idx = blockIdx.x * blockDim.x + threadIdx.x;
    if (idx >= NS * 32) return;
    int s = idx >> 5, j = idx & 31;
    float invf = (float)exp(-(double)j * (log(10000.0) / 32.0));
    float ang = (float)s * invf;
    g_cos[idx] = (float)cos((double)ang);
    g_sin[idx] = (float)sin((double)ang);
}

// mask [B,S,S] int32 -> bitwords
__global__ void mask_bits_kernel(const int* __restrict__ mask) {
    int gw = (blockIdx.x * blockDim.x + threadIdx.x) >> 5;
    int lane = threadIdx.x & 31;
    if (gw >= NB * NS) return;
    const int* mrow = mask + (size_t)gw * NS;
    unsigned* dst = g_mb + (size_t)gw * 64;
    for (int wd = 0; wd < 64; wd++) {
        unsigned bits = __ballot_sync(0xffffffffu, mrow[wd * 32 + lane] != 0);
        if (lane == 0) dst[wd] = bits;
    }
}

// batched fp32->fp16, 4 float4 per thread (MLP=4)
__global__ void f2h_multi_kernel(const float* s0, const float* s1,
                                 const float* s2, const float* s3,
                                 __half* __restrict__ out, int n4) {
    int i = (blockIdx.x * blockDim.x + threadIdx.x) * 4;
    if (i >= n4) return;
    const float* srcs[4] = {s0, s1, s2, s3};
    const float* in = srcs[blockIdx.y];
    __half* o = out + (size_t)blockIdx.y * n4 * 4;
    float4 v0 = ((const float4*)in)[i];
    float4 v1 = ((const float4*)in)[i + 1];
    float4 v2 = ((const float4*)in)[i + 2];
    float4 v3 = ((const float4*)in)[i + 3];
    uint4 u;
    u.x = packh2(v0.x, v0.y); u.y = packh2(v0.z, v0.w);
    u.z = packh2(v1.x, v1.y); u.w = packh2(v1.z, v1.w);
    *(uint4*)(o + (size_t)i * 4) = u;
    u.x = packh2(v2.x, v2.y); u.y = packh2(v2.z, v2.w);
    u.z = packh2(v3.x, v3.y); u.w = packh2(v3.z, v3.w);
    *(uint4*)(o + (size_t)i * 4 + 8) = u;
}

// ---------------------------------------------------------------------------
// Shared GEMM mainloop: 128m x 256n CTA tile, cp.async 3 stages, fp32 accum.
// ---------------------------------------------------------------------------
#define LP 40
#define LIN_SMEM (3*(128+256)*LP*2)   // 92160 bytes

struct LinCtx {
    int tid, w, lane, grp, qid, wm, wn;
    int lane15, acolsel, b_rowoff, bcolsel;
};

__device__ __forceinline__ void gemm_main(
    const __half* __restrict__ Ah, const __half* __restrict__ Wh,
    int m0, int n0, __half* lsm, const LinCtx& c, float acc[4][8][4])
{
    __half* AsB = lsm;
    __half* BsB = lsm + 3 * 128 * LP;
    unsigned As_u = (unsigned)__cvta_generic_to_shared(AsB);
    unsigned Bs_u = (unsigned)__cvta_generic_to_shared(BsB);

    int arow = c.tid >> 2, aseg = c.tid & 3;
    const __half* abase = Ah + (size_t)(m0 + arow) * NDIM + aseg * 8;
    const __half* bbase = Wh + (size_t)(n0 + arow) * NDIM + aseg * 8;

    #pragma unroll
    for (int mt = 0; mt < 4; mt++)
        #pragma unroll
        for (int nt = 0; nt < 8; nt++)
            #pragma unroll
            for (int r = 0; r < 4; r++) acc[mt][nt][r] = 0.f;

    auto issue = [&](int kt, int st) {
        unsigned adst = As_u + (st * 128 * LP) * 2;
        unsigned bdst = Bs_u + (st * 256 * LP) * 2;
        int koff = kt * 32;
        #pragma unroll
        for (int i = 0; i < 2; i++) {
            int row = arow + i * 64;
            CP16(adst + (row * LP + aseg * 8) * 2, abase + (size_t)i * 64 * NDIM + koff);
        }
        #pragma unroll
        for (int i = 0; i < 4; i++) {
            int row = arow + i * 64;
            CP16(bdst + (row * LP + aseg * 8) * 2, bbase + (size_t)i * 64 * NDIM + koff);
        }
    };

    issue(0, 0); CP_COMMIT();
    issue(1, 1); CP_COMMIT();

    const int NKT = NDIM / 32;
    int st = 0;
    for (int kt = 0; kt < NKT; kt++) {
        CP_WAIT1();
        __syncthreads();
        if (kt + 2 < NKT) {
            int nst = st + 2; if (nst >= 3) nst -= 3;
            issue(kt + 2, nst);
        }
        CP_COMMIT();

        const __half* Asst = AsB + st * 128 * LP;
        const __half* Bsst = BsB + st * 256 * LP;
        #pragma unroll
        for (int sl = 0; sl < 2; sl++) {
            int kof = sl * 16;
            unsigned afr[4][4], bfr[8][2];
            #pragma unroll
            for (int mt = 0; mt < 4; mt++)
                ldsm4(afr[mt][0], afr[mt][1], afr[mt][2], afr[mt][3],
                      Asst + (c.wm + mt * 16 + c.lane15) * LP + kof + c.acolsel);
            #pragma unroll
            for (int ntp = 0; ntp < 4; ntp++) {
                unsigned r0, r1, r2, r3;
                ldsm4(r0, r1, r2, r3,
                      Bsst + (c.wn + ntp * 16 + c.b_rowoff) * LP + kof + c.bcolsel);
                bfr[ntp*2][0]   = r0; bfr[ntp*2][1]   = r1;
                bfr[ntp*2+1][0] = r2; bfr[ntp*2+1][1] = r3;
            }
            #pragma unroll
            for (int mt = 0; mt < 4; mt++)
                #pragma unroll
                for (int nt = 0; nt < 8; nt++)
                    mma_f16(acc[mt][nt], afr[mt][0], afr[mt][1], afr[mt][2], afr[mt][3],
                            bfr[nt][0], bfr[nt][1]);
        }
        st++; if (st >= 3) st = 0;
    }
}

__device__ __forceinline__ LinCtx make_ctx() {
    LinCtx c;
    c.tid  = threadIdx.x;
    c.w    = c.tid >> 5;
    c.lane = c.tid & 31;
    c.grp  = c.lane >> 2;
    c.qid  = c.lane & 3;
    c.wm   = (c.w & 1) * 64;
    c.wn   = (c.w >> 1) * 64;
    c.lane15   = c.lane & 15;
    c.acolsel  = (c.lane >> 4) << 3;
    c.b_rowoff = (c.lane & 7) + ((c.lane >> 4) << 3);
    c.bcolsel  = ((c.lane >> 3) & 1) << 3;
    return c;
}

// ---------------------------------------------------------------------------
// Fused QKV projection: grid (4, 32, 3).  z=0 Q (RoPE, pre-scaled -> g_qh),
// z=1 K (RoPE -> outK fp32 + g_kh half), z=2 V (outV fp32 + g_vTh half).
// ---------------------------------------------------------------------------
__global__ __launch_bounds__(256)
void qkv_tc_kernel(const float* __restrict__ bq, const float* __restrict__ bk,
                   const float* __restrict__ bv, float* __restrict__ outK,
                   float* __restrict__ outV)
{
    extern __shared__ __align__(16) __half lsm[];
    LinCtx c = make_ctx();
    int z = blockIdx.z;
    int m0 = blockIdx.y << 7, n0 = blockIdx.x << 8;

    const __half* Ah = g_inh + (size_t)z * NM * NDIM;
    const __half* Wh = g_wh + (size_t)z * NDIM * NDIM;
    const float* bias = (z == 0) ? bq : (z == 1) ? bk : bv;

    float acc[4][8][4];
    gemm_main(Ah, Wh, m0, n0, lsm, c, acc);

    if (z == 2) {
        #pragma unroll
        for (int mt = 0; mt < 4; mt++) {
            #pragma unroll
            for (int nt = 0; nt < 8; nt++) {
                int n = n0 + c.wn + nt * 8 + (c.qid << 1);
                float bx = bias[n], by = bias[n + 1];
                int h = n >> 6, d = n & 63;
                #pragma unroll
                for (int half = 0; half < 2; half++) {
                    int m = m0 + c.wm + mt * 16 + c.grp + half * 8;
                    int b = m >> 11, s = m & (NS - 1);
                    float vx = acc[mt][nt][half * 2 + 0] + bx;
                    float vy = acc[mt][nt][half * 2 + 1] + by;
                    size_t bh = (size_t)((b << 4) + h);
                    *(float2*)&outV[(bh * NS + s) * HD + d] = make_float2(vx, vy);
                    __half* vt = g_vTh + bh * HD * NS + (size_t)d * NS + s;
                    vt[0]  = __float2half_rn(vx);
                    vt[NS] = __float2half_rn(vy);
                }
            }
        }
    } else {
        int h = (n0 + c.wn) >> 6;
        #pragma unroll
        for (int mt = 0; mt < 4; mt++) {
            #pragma unroll
            for (int half = 0; half < 2; half++) {
                int m = m0 + c.wm + mt * 16 + c.grp + half * 8;
                int b = m >> 11, s = m & (NS - 1);
                size_t rowbase = (((size_t)((b << 4) + h) * NS + s)) * HD;
                #pragma unroll
                for (int ntp = 0; ntp < 4; ntp++) {
                    int n = n0 + c.wn + ntp * 8 + (c.qid << 1);
                    int d = ntp * 8 + (c.qid << 1);
                    float x1a = acc[mt][ntp][half*2+0]   + bias[n];
                    float x1b = acc[mt][ntp][half*2+1]   + bias[n+1];
                    float x2a = acc[mt][ntp+4][half*2+0] + bias[n+32];
                    float x2b = acc[mt][ntp+4][half*2+1] + bias[n+33];
                    float2 cv = *(const float2*)&g_cos[(s << 5) + d];
                    float2 sv = *(const float2*)&g_sin[(s << 5) + d];
                    float o1a = x1a * cv.x - x2a * sv.x;
                    float o1b = x1b * cv.y - x2b * sv.y;
                    float o2a = x2a * cv.x + x1a * sv.x;
                    float o2b = x2b * cv.y + x1b * sv.y;
                    if (z == 0) {
                        // pre-scale q by 0.125*log2(e) for exp2-domain softmax
                        *(unsigned*)&g_qh[rowbase + d] =
                            packh2(o1a * SCALE2, o1b * SCALE2);
                        *(unsigned*)&g_qh[rowbase + d + 32] =
                            packh2(o2a * SCALE2, o2b * SCALE2);
                    } else {
                        *(float2*)&outK[rowbase + d]      = make_float2(o1a, o1b);
                        *(float2*)&outK[rowbase + d + 32] = make_float2(o2a, o2b);
                        *(unsigned*)&g_kh[rowbase + d]      = packh2(o1a, o1b);
                        *(unsigned*)&g_kh[rowbase + d + 32] = packh2(o2a, o2b);
                    }
                }
            }
        }
    }
}

// Out-projection: flat fp32 epilogue.
__global__ __launch_bounds__(256)
void out_tc_kernel(const float* __restrict__ bias, float* __restrict__ dst)
{
    extern __shared__ __align__(16) __half lsm[];
    LinCtx c = make_ctx();
    int m0 = blockIdx.y << 7, n0 = blockIdx.x << 8;

    float acc[4][8][4];
    gemm_main(g_ah, g_wh + 3 * (size_t)NDIM * NDIM, m0, n0, lsm, c, acc);

    #pragma unroll
    for (int mt = 0; mt < 4; mt++) {
        #pragma unroll
        for (int nt = 0; nt < 8; nt++) {
            int n = n0 + c.wn + nt * 8 + (c.qid << 1);
            float bx = bias[n], by = bias[n + 1];
            #pragma unroll
            for (int half = 0; half < 2; half++) {
                int m = m0 + c.wm + mt * 16 + c.grp + half * 8;
                float2 v;
                v.x = acc[mt][nt][half * 2 + 0] + bx;
                v.y = acc[mt][nt][half * 2 + 1] + by;
                *(float2*)&dst[(size_t)m * NDIM + n] = v;
            }
        }
    }
}

// ---------------------------------------------------------------------------
// FP16 MMA flash attention: 4-stage cp.async (wait_group 2), P in registers,
// Q pre-scaled (mask = bare select), lazy O-rescale via ballot.
// Smem (halves): Qs[128][72] | K 4x[64][72] | V 4x[64][72] = 92160 B.
// ---------------------------------------------------------------------------
#define APH 72
#define ATTN_SMEM ((128*APH + 4*64*APH + 4*64*APH) * 2)

__global__ __launch_bounds__(256, 2)
void attn_tc_kernel()
{
    extern __shared__ __align__(16) __half asm_h[];
    __half* Qs  = asm_h;
    __half* Kst = asm_h + 128 * APH;
    __half* Vst = Kst + 4 * 64 * APH;
    unsigned K_u = (unsigned)__cvta_generic_to_shared(Kst);
    unsigned V_u = (unsigned)__cvta_generic_to_shared(Vst);

    int tid = threadIdx.x;
    int w = tid >> 5, lane = tid & 31;
    int grp = lane >> 2, qid = lane & 3;
    int wm = w << 4;
    int bh = blockIdx.y;
    int b = bh >> 4, h = bh & 15;
    int q0 = blockIdx.x << 7;

    int lane15   = lane & 15;
    int acolsel  = (lane >> 4) << 3;
    int b_rowoff = (lane & 7) + ((lane >> 4) << 3);
    int bcolsel  = ((lane >> 3) & 1) << 3;

    const __half* qptr  = g_qh + ((size_t)bh * NS + q0) * HD;
    const __half* kptr  = g_kh + (size_t)bh * NS * HD;
    const __half* vTptr = g_vTh + (size_t)bh * HD * NS;
    const unsigned* mb0 = g_mb + (size_t)(b * NS + q0 + wm + grp) * 64;
    const unsigned* mb1 = mb0 + 8 * 64;

    #pragma unroll
    for (int i = 0; i < 4; i++) {
        int cc = tid + (i << 8);
        int row = cc >> 3, seg = cc & 7;
        *(uint4*)&Qs[row * APH + seg * 8] = *(const uint4*)(qptr + row * HD + seg * 8);
    }

    int crow = tid >> 3, cseg = tid & 7;
    auto issueKV = [&](int t, int st) {
        int k0 = t << 6;
        #pragma unroll
        for (int i = 0; i < 2; i++) {
            int row = crow + i * 32;
            CP16(K_u + ((st * 64 + row) * APH + cseg * 8) * 2,
                 kptr + (size_t)(k0 + row) * HD + cseg * 8);
            CP16(V_u + ((st * 64 + row) * APH + cseg * 8) * 2,
                 vTptr + (size_t)row * NS + k0 + cseg * 8);
        }
    };

    issueKV(0, 0); CP_COMMIT();
    issueKV(1, 1); CP_COMMIT();
    issueKV(2, 2); CP_COMMIT();

    float o[8][4];
    #pragma unroll
    for (int nt = 0; nt < 8; nt++)
        #pragma unroll
        for (int r = 0; r < 4; r++) o[nt][r] = 0.f;
    float m0 = -3.0e38f, m1 = -3.0e38f, l0 = 0.f, l1 = 0.f;

    const int NT = NS / 64;
    int st = 0;
    for (int t = 0; t < NT; t++) {
        CP_WAIT2();
        __syncthreads();
        if (t + 3 < NT) issueKV(t + 3, (st + 3) & 3);
        CP_COMMIT();

        const __half* Ks = Kst + st * 64 * APH;
        const __half* Vs = Vst + st * 64 * APH;
        int k0 = t << 6;

        float sc[8][4];
        #pragma unroll
        for (int nt = 0; nt < 8; nt++)
            #pragma unroll
            for (int r = 0; r < 4; r++) sc[nt][r] = 0.f;

        #pragma unroll
        for (int kk = 0; kk < 4; kk++) {
            unsigned a0, a1, a2, a3;
            ldsm4(a0, a1, a2, a3, &Qs[(wm + lane15) * APH + kk * 16 + acolsel]);
            #pragma unroll
            for (int ntp = 0; ntp < 4; ntp++) {
                unsigned r0, r1, r2, r3;
                ldsm4(r0, r1, r2, r3,
                      Ks + (ntp * 16 + b_rowoff) * APH + kk * 16 + bcolsel);
                mma_f16(sc[ntp*2],   a0, a1, a2, a3, r0, r1);
                mma_f16(sc[ntp*2+1], a0, a1, a2, a3, r2, r3);
            }
        }

        // mask only (scores already in exp2 domain via pre-scaled Q)
        unsigned long long w0 = *(const unsigned long long*)(mb0 + (k0 >> 5));
        unsigned long long w1 = *(const unsigned long long*)(mb1 + (k0 >> 5));
        #pragma unroll
        for (int nt = 0; nt < 8; nt++) {
            int p = nt * 8 + (qid << 1);
            sc[nt][0] = ((w0 >> p)     & 1) ? sc[nt][0] : -1e30f;
            sc[nt][1] = ((w0 >> (p+1)) & 1) ? sc[nt][1] : -1e30f;
            sc[nt][2] = ((w1 >> p)     & 1) ? sc[nt][2] : -1e30f;
            sc[nt][3] = ((w1 >> (p+1)) & 1) ? sc[nt][3] : -1e30f;
        }

        float mx0 = -3.0e38f, mx1 = -3.0e38f;
        #pragma unroll
        for (int nt = 0; nt < 8; nt++) {
            mx0 = fmaxf(mx0, fmaxf(sc[nt][0], sc[nt][1]));
            mx1 = fmaxf(mx1, fmaxf(sc[nt][2], sc[nt][3]));
        }
        mx0 = fmaxf(mx0, __shfl_xor_sync(0xffffffffu, mx0, 1));
        mx0 = fmaxf(mx0, __shfl_xor_sync(0xffffffffu, mx0, 2));
        mx1 = fmaxf(mx1, __shfl_xor_sync(0xffffffffu, mx1, 1));
        mx1 = fmaxf(mx1, __shfl_xor_sync(0xffffffffu, mx1, 2));

        float mn0 = fmaxf(m0, mx0), mn1 = fmaxf(m1, mx1);
        bool maxup = (mn0 > m0) || (mn1 > m1);
        unsigned anyup = __ballot_sync(0xffffffffu, maxup);

        unsigned pfrag[8][2];
        float ps0 = 0.f, ps1 = 0.f;
        #pragma unroll
        for (int nt = 0; nt < 8; nt++) {
            __half2 e0 = h2exp2(__floats2half2_rn(sc[nt][0] - mn0, sc[nt][1] - mn0));
            __half2 e1 = h2exp2(__floats2half2_rn(sc[nt][2] - mn1, sc[nt][3] - mn1));
            pfrag[nt][0] = *(unsigned*)&e0;
            pfrag[nt][1] = *(unsigned*)&e1;
            float2 f0 = __half22float2(e0);
            float2 f1 = __half22float2(e1);
            ps0 += f0.x + f0.y;
            ps1 += f1.x + f1.y;
        }
        ps0 += __shfl_xor_sync(0xffffffffu, ps0, 1);
        ps0 += __shfl_xor_sync(0xffffffffu, ps0, 2);
        ps1 += __shfl_xor_sync(0xffffffffu, ps1, 1);
        ps1 += __shfl_xor_sync(0xffffffffu, ps1, 2);

        if (anyup) {
            float corr0 = fex2(m0 - mn0), corr1 = fex2(m1 - mn1);
            m0 = mn0; m1 = mn1;
            l0 = l0 * corr0 + ps0;
            l1 = l1 * corr1 + ps1;
            #pragma unroll
            for (int nt = 0; nt < 8; nt++) {
                o[nt][0] *= corr0; o[nt][1] *= corr0;
                o[nt][2] *= corr1; o[nt][3] *= corr1;
            }
        } else {
            l0 += ps0;
            l1 += ps1;
        }

        #pragma unroll
        for (int kk = 0; kk < 4; kk++) {
            unsigned a0 = pfrag[2*kk][0];
            unsigned a1 = pfrag[2*kk][1];
            unsigned a2 = pfrag[2*kk+1][0];
            unsigned a3 = pfrag[2*kk+1][1];
            #pragma unroll
            for (int ntp = 0; ntp < 4; ntp++) {
                unsigned r0, r1, r2, r3;
                ldsm4(r0, r1, r2, r3,
                      Vs + (ntp * 16 + b_rowoff) * APH + kk * 16 + bcolsel);
                mma_f16(o[ntp*2],   a0, a1, a2, a3, r0, r1);
                mma_f16(o[ntp*2+1], a0, a1, a2, a3, r2, r3);
            }
        }
        st = (st + 1) & 3;
    }

    float inv0 = 1.0f / l0, inv1 = 1.0f / l1;
    int r0 = q0 + wm + grp, r1 = r0 + 8;
    #pragma unroll
    for (int nt = 0; nt < 8; nt++) {
        int col = h * HD + nt * 8 + (qid << 1);
        *(unsigned*)&g_ah[((size_t)b * NS + r0) * NDIM + col] =
            packh2(o[nt][0] * inv0, o[nt][1] * inv0);
        *(unsigned*)&g_ah[((size_t)b * NS + r1) * NDIM + col] =
            packh2(o[nt][2] * inv1, o[nt][3] * inv1);
    }
}

// ---------------------------------------------------------------------------
extern "C" void kernel_launch(void* const* d_in, const int* in_sizes, int n_in,
                              void* d_out, int out_size) {
    const float* query = (const float*)d_in[0];
    const float* key   = (const float*)d_in[1];
    const float* value = (const float*)d_in[2];
    const int*   mask  = (const int*)d_in[3];
    const float* Wq = (const float*)d_in[4];
    const float* bq = (const float*)d_in[5];
    const float* Wk = (const float*)d_in[6];
    const float* bk = (const float*)d_in[7];
    const float* Wv = (const float*)d_in[8];
    const float* bv = (const float*)d_in[9];
    const float* Wo = (const float*)d_in[10];
    const float* bo = (const float*)d_in[11];

    float* out  = (float*)d_out;                 // [B,S,1024]
    float* outK = out + OUT_ELEMS;               // [B,H,S,64] (post-RoPE k)
    float* outV = out + 2 * (size_t)OUT_ELEMS;   // [B,H,S,64] (v)

    __half* g_inh_p; cudaGetSymbolAddress((void**)&g_inh_p, g_inh);
    __half* g_wh_p;  cudaGetSymbolAddress((void**)&g_wh_p, g_wh);

    static int smem_set = 0;
    if (!smem_set) {
        cudaFuncSetAttribute(qkv_tc_kernel, cudaFuncAttributeMaxDynamicSharedMemorySize,
                             LIN_SMEM);
        cudaFuncSetAttribute(out_tc_kernel, cudaFuncAttributeMaxDynamicSharedMemorySize,
                             LIN_SMEM);
        cudaFuncSetAttribute(attn_tc_kernel, cudaFuncAttributeMaxDynamicSharedMemorySize,
                             ATTN_SMEM);
        smem_set = 1;
    }

    const int A4 = NM * NDIM / 4;
    const int W4 = NDIM * NDIM / 4;

    rope_table_kernel<<<(NS * 32 + 255) / 256, 256>>>();
    mask_bits_kernel<<<(NB * NS * 32 + 255) / 256, 256>>>(mask);

    dim3 wgrid4(W4 / 1024, 4);
    f2h_multi_kernel<<<wgrid4, 256>>>(Wq, Wk, Wv, Wo, g_wh_p, W4);
    dim3 igrid3(A4 / 1024, 3);
    f2h_multi_kernel<<<igrid3, 256>>>(query, key, value, value, g_inh_p, A4);

    dim3 qkvgrid(NDIM / 256, NM / 128, 3);   // (4, 32, 3) = 384 CTAs
    qkv_tc_kernel<<<qkvgrid, 256, LIN_SMEM>>>(bq, bk, bv, outK, outV);

    dim3 agrid(NS / 128, NB * NH);           // (16, 32)
    attn_tc_kernel<<<agrid, 256, ATTN_SMEM>>>();

    dim3 ogrid(NDIM / 256, NM / 128);        // (4, 32)
    out_tc_kernel<<<ogrid, 256, LIN_SMEM>>>(bo, out);
}

// round 16
// speedup vs baseline: 1.0047x; 1.0047x over previous
#include <cuda_runtime.h>
#include <cuda_fp16.h>
#include <math.h>

#define NB 2
#define NS 2048
#define NH 16
#define HD 64
#define NDIM 1024
#define NM (NB*NS)
#define OUT_ELEMS (NB*NS*NDIM)   // 4194304 per tensor (out, k, v)

// Scratch (allocation-free rule: __device__ globals)
__device__ __align__(256) __half g_ah[NM*NDIM];       // ctx half (A of out-proj)
__device__ __align__(256) __half g_inh[3*NM*NDIM];    // half query/key/value inputs
__device__ __align__(256) __half g_wh[4*NDIM*NDIM];   // half Wq/Wk/Wv/Wo
__device__ __align__(256) __half g_qh[NB*NH*NS*HD];   // half Q (post-RoPE, pre-scaled)
__device__ __align__(256) __half g_kh[NB*NH*NS*HD];   // half K (post-RoPE)
__device__ __align__(256) __half g_vTh[NB*NH*HD*NS];  // half V transposed [b,h,d,s]
__device__ __align__(256) unsigned g_mb[NB*NS*64];    // mask bitwords
__device__ float g_cos[NS*32];
__device__ float g_sin[NS*32];

#define SCALE2 0.18033688011112042f   // 0.125 * log2(e)

__device__ __forceinline__ unsigned packh2(float x, float y) {
    __half2 h = __floats2half2_rn(x, y);
    return *(unsigned*)&h;
}
__device__ __forceinline__ float fex2(float x) {
    float r; asm("ex2.approx.ftz.f32 %0, %1;" : "=f"(r) : "f"(x)); return r;
}
__device__ __forceinline__ void mma_f16(float c[4], unsigned a0, unsigned a1,
                                        unsigned a2, unsigned a3,
                                        unsigned b0, unsigned b1) {
    asm volatile(
        "mma.sync.aligned.m16n8k16.row.col.f32.f16.f16.f32 "
        "{%0,%1,%2,%3}, {%4,%5,%6,%7}, {%8,%9}, {%0,%1,%2,%3};"
        : "+f"(c[0]), "+f"(c[1]), "+f"(c[2]), "+f"(c[3])
        : "r"(a0), "r"(a1), "r"(a2), "r"(a3), "r"(b0), "r"(b1));
}
__device__ __forceinline__ void ldsm4(unsigned &r0, unsigned &r1, unsigned &r2,
                                      unsigned &r3, const void* p) {
    unsigned a = (unsigned)__cvta_generic_to_shared(p);
    asm volatile("ldmatrix.sync.aligned.m8n8.x4.shared.b16 {%0,%1,%2,%3}, [%4];"
                 : "=r"(r0), "=r"(r1), "=r"(r2), "=r"(r3) : "r"(a));
}
#define CP16(dst_u32, src_ptr) \
    asm volatile("cp.async.ca.shared.global [%0], [%1], 16;" \
                 :: "r"(dst_u32), "l"(src_ptr))
#define CP_COMMIT() asm volatile("cp.async.commit_group;" ::: "memory")
#define CP_WAIT1()  asm volatile("cp.async.wait_group 1;" ::: "memory")

// ---------------------------------------------------------------------------
// RoPE tables
// ---------------------------------------------------------------------------
__global__ void rope_table_kernel() {
    int idx = blockIdx.x * blockDim.x + threadIdx.x;
    if (idx >= NS * 32) return;
    int s = idx >> 5, j = idx & 31;
    float invf = (float)exp(-(double)j * (log(10000.0) / 32.0));
    float ang = (float)s * invf;
    g_cos[idx] = (float)cos((double)ang);
    g_sin[idx] = (float)sin((double)ang);
}

// mask [B,S,S] int32 -> bitwords
__global__ void mask_bits_kernel(const int* __restrict__ mask) {
    int gw = (blockIdx.x * blockDim.x + threadIdx.x) >> 5;
    int lane = threadIdx.x & 31;
    if (gw >= NB * NS) return;
    const int* mrow = mask + (size_t)gw * NS;
    unsigned* dst = g_mb + (size_t)gw * 64;
    for (int wd = 0; wd < 64; wd++) {
        unsigned bits = __ballot_sync(0xffffffffu, mrow[wd * 32 + lane] != 0);
        if (lane == 0) dst[wd] = bits;
    }
}

// batched fp32->fp16, 4 float4 per thread
__global__ void f2h_multi_kernel(const float* s0, const float* s1,
                                 const float* s2, const float* s3,
                                 __half* __restrict__ out, int n4) {
    int i = (blockIdx.x * blockDim.x + threadIdx.x) * 4;
    if (i >= n4) return;
    const float* srcs[4] = {s0, s1, s2, s3};
    const float* in = srcs[blockIdx.y];
    __half* o = out + (size_t)blockIdx.y * n4 * 4;
    float4 v0 = ((const float4*)in)[i];
    float4 v1 = ((const float4*)in)[i + 1];
    float4 v2 = ((const float4*)in)[i + 2];
    float4 v3 = ((const float4*)in)[i + 3];
    uint4 u;
    u.x = packh2(v0.x, v0.y); u.y = packh2(v0.z, v0.w);
    u.z = packh2(v1.x, v1.y); u.w = packh2(v1.z, v1.w);
    *(uint4*)(o + (size_t)i * 4) = u;
    u.x = packh2(v2.x, v2.y); u.y = packh2(v2.z, v2.w);
    u.z = packh2(v3.x, v3.y); u.w = packh2(v3.z, v3.w);
    *(uint4*)(o + (size_t)i * 4 + 8) = u;
}

// ---------------------------------------------------------------------------
// Shared GEMM mainloop: 128m x 256n CTA tile, cp.async 3 stages, fp32 accum.
// ---------------------------------------------------------------------------
#define LP 40
#define LIN_SMEM (3*(128+256)*LP*2)   // 92160 bytes

struct LinCtx {
    int tid, w, lane, grp, qid, wm, wn;
    int lane15, acolsel, b_rowoff, bcolsel;
};

__device__ __forceinline__ void gemm_main(
    const __half* __restrict__ Ah, const __half* __restrict__ Wh,
    int m0, int n0, __half* lsm, const LinCtx& c, float acc[4][8][4])
{
    __half* AsB = lsm;
    __half* BsB = lsm + 3 * 128 * LP;
    unsigned As_u = (unsigned)__cvta_generic_to_shared(AsB);
    unsigned Bs_u = (unsigned)__cvta_generic_to_shared(BsB);

    int arow = c.tid >> 2, aseg = c.tid & 3;
    const __half* abase = Ah + (size_t)(m0 + arow) * NDIM + aseg * 8;
    const __half* bbase = Wh + (size_t)(n0 + arow) * NDIM + aseg * 8;

    #pragma unroll
    for (int mt = 0; mt < 4; mt++)
        #pragma unroll
        for (int nt = 0; nt < 8; nt++)
            #pragma unroll
            for (int r = 0; r < 4; r++) acc[mt][nt][r] = 0.f;

    auto issue = [&](int kt, int st) {
        unsigned adst = As_u + (st * 128 * LP) * 2;
        unsigned bdst = Bs_u + (st * 256 * LP) * 2;
        int koff = kt * 32;
        #pragma unroll
        for (int i = 0; i < 2; i++) {
            int row = arow + i * 64;
            CP16(adst + (row * LP + aseg * 8) * 2, abase + (size_t)i * 64 * NDIM + koff);
        }
        #pragma unroll
        for (int i = 0; i < 4; i++) {
            int row = arow + i * 64;
            CP16(bdst + (row * LP + aseg * 8) * 2, bbase + (size_t)i * 64 * NDIM + koff);
        }
    };

    issue(0, 0); CP_COMMIT();
    issue(1, 1); CP_COMMIT();

    const int NKT = NDIM / 32;
    int st = 0;
    for (int kt = 0; kt < NKT; kt++) {
        CP_WAIT1();
        __syncthreads();
        if (kt + 2 < NKT) {
            int nst = st + 2; if (nst >= 3) nst -= 3;
            issue(kt + 2, nst);
        }
        CP_COMMIT();

        const __half* Asst = AsB + st * 128 * LP;
        const __half* Bsst = BsB + st * 256 * LP;
        #pragma unroll
        for (int sl = 0; sl < 2; sl++) {
            int kof = sl * 16;
            unsigned afr[4][4], bfr[8][2];
            #pragma unroll
            for (int mt = 0; mt < 4; mt++)
                ldsm4(afr[mt][0], afr[mt][1], afr[mt][2], afr[mt][3],
                      Asst + (c.wm + mt * 16 + c.lane15) * LP + kof + c.acolsel);
            #pragma unroll
            for (int ntp = 0; ntp < 4; ntp++) {
                unsigned r0, r1, r2, r3;
                ldsm4(r0, r1, r2, r3,
                      Bsst + (c.wn + ntp * 16 + c.b_rowoff) * LP + kof + c.bcolsel);
                bfr[ntp*2][0]   = r0; bfr[ntp*2][1]   = r1;
                bfr[ntp*2+1][0] = r2; bfr[ntp*2+1][1] = r3;
            }
            #pragma unroll
            for (int mt = 0; mt < 4; mt++)
                #pragma unroll
                for (int nt = 0; nt < 8; nt++)
                    mma_f16(acc[mt][nt], afr[mt][0], afr[mt][1], afr[mt][2], afr[mt][3],
                            bfr[nt][0], bfr[nt][1]);
        }
        st++; if (st >= 3) st = 0;
    }
}

__device__ __forceinline__ LinCtx make_ctx() {
    LinCtx c;
    c.tid  = threadIdx.x;
    c.w    = c.tid >> 5;
    c.lane = c.tid & 31;
    c.grp  = c.lane >> 2;
    c.qid  = c.lane & 3;
    c.wm   = (c.w & 1) * 64;
    c.wn   = (c.w >> 1) * 64;
    c.lane15   = c.lane & 15;
    c.acolsel  = (c.lane >> 4) << 3;
    c.b_rowoff = (c.lane & 7) + ((c.lane >> 4) << 3);
    c.bcolsel  = ((c.lane >> 3) & 1) << 3;
    return c;
}

// ---------------------------------------------------------------------------
// Fused QKV projection (unchanged from R15).
// ---------------------------------------------------------------------------
__global__ __launch_bounds__(256)
void qkv_tc_kernel(const float* __restrict__ bq, const float* __restrict__ bk,
                   const float* __restrict__ bv, float* __restrict__ outK,
                   float* __restrict__ outV)
{
    extern __shared__ __align__(16) __half lsm[];
    LinCtx c = make_ctx();
    int z = blockIdx.z;
    int m0 = blockIdx.y << 7, n0 = blockIdx.x << 8;

    const __half* Ah = g_inh + (size_t)z * NM * NDIM;
    const __half* Wh = g_wh + (size_t)z * NDIM * NDIM;
    const float* bias = (z == 0) ? bq : (z == 1) ? bk : bv;

    float acc[4][8][4];
    gemm_main(Ah, Wh, m0, n0, lsm, c, acc);

    if (z == 2) {
        #pragma unroll
        for (int mt = 0; mt < 4; mt++) {
            #pragma unroll
            for (int nt = 0; nt < 8; nt++) {
                int n = n0 + c.wn + nt * 8 + (c.qid << 1);
                float bx = bias[n], by = bias[n + 1];
                int h = n >> 6, d = n & 63;
                #pragma unroll
                for (int half = 0; half < 2; half++) {
                    int m = m0 + c.wm + mt * 16 + c.grp + half * 8;
                    int b = m >> 11, s = m & (NS - 1);
                    float vx = acc[mt][nt][half * 2 + 0] + bx;
                    float vy = acc[mt][nt][half * 2 + 1] + by;
                    size_t bh = (size_t)((b << 4) + h);
                    *(float2*)&outV[(bh * NS + s) * HD + d] = make_float2(vx, vy);
                    __half* vt = g_vTh + bh * HD * NS + (size_t)d * NS + s;
                    vt[0]  = __float2half_rn(vx);
                    vt[NS] = __float2half_rn(vy);
                }
            }
        }
    } else {
        int h = (n0 + c.wn) >> 6;
        #pragma unroll
        for (int mt = 0; mt < 4; mt++) {
            #pragma unroll
            for (int half = 0; half < 2; half++) {
                int m = m0 + c.wm + mt * 16 + c.grp + half * 8;
                int b = m >> 11, s = m & (NS - 1);
                size_t rowbase = (((size_t)((b << 4) + h) * NS + s)) * HD;
                #pragma unroll
                for (int ntp = 0; ntp < 4; ntp++) {
                    int n = n0 + c.wn + ntp * 8 + (c.qid << 1);
                    int d = ntp * 8 + (c.qid << 1);
                    float x1a = acc[mt][ntp][half*2+0]   + bias[n];
                    float x1b = acc[mt][ntp][half*2+1]   + bias[n+1];
                    float x2a = acc[mt][ntp+4][half*2+0] + bias[n+32];
                    float x2b = acc[mt][ntp+4][half*2+1] + bias[n+33];
                    float2 cv = *(const float2*)&g_cos[(s << 5) + d];
                    float2 sv = *(const float2*)&g_sin[(s << 5) + d];
                    float o1a = x1a * cv.x - x2a * sv.x;
                    float o1b = x1b * cv.y - x2b * sv.y;
                    float o2a = x2a * cv.x + x1a * sv.x;
                    float o2b = x2b * cv.y + x1b * sv.y;
                    if (z == 0) {
                        *(unsigned*)&g_qh[rowbase + d] =
                            packh2(o1a * SCALE2, o1b * SCALE2);
                        *(unsigned*)&g_qh[rowbase + d + 32] =
                            packh2(o2a * SCALE2, o2b * SCALE2);
                    } else {
                        *(float2*)&outK[rowbase + d]      = make_float2(o1a, o1b);
                        *(float2*)&outK[rowbase + d + 32] = make_float2(o2a, o2b);
                        *(unsigned*)&g_kh[rowbase + d]      = packh2(o1a, o1b);
                        *(unsigned*)&g_kh[rowbase + d + 32] = packh2(o2a, o2b);
                    }
                }
            }
        }
    }
}

// Out-projection: flat fp32 epilogue.
__global__ __launch_bounds__(256)
void out_tc_kernel(const float* __restrict__ bias, float* __restrict__ dst)
{
    extern __shared__ __align__(16) __half lsm[];
    LinCtx c = make_ctx();
    int m0 = blockIdx.y << 7, n0 = blockIdx.x << 8;

    float acc[4][8][4];
    gemm_main(g_ah, g_wh + 3 * (size_t)NDIM * NDIM, m0, n0, lsm, c, acc);

    #pragma unroll
    for (int mt = 0; mt < 4; mt++) {
        #pragma unroll
        for (int nt = 0; nt < 8; nt++) {
            int n = n0 + c.wn + nt * 8 + (c.qid << 1);
            float bx = bias[n], by = bias[n + 1];
            #pragma unroll
            for (int half = 0; half < 2; half++) {
                int m = m0 + c.wm + mt * 16 + c.grp + half * 8;
                float2 v;
                v.x = acc[mt][nt][half * 2 + 0] + bx;
                v.y = acc[mt][nt][half * 2 + 1] + by;
                *(float2*)&dst[(size_t)m * NDIM + n] = v;
            }
        }
    }
}

// ---------------------------------------------------------------------------
// FP16 MMA flash attention, BQ=256: each warp owns two 16-row q-blocks.
// K/V loaded once per tile serve both halves.  256 CTAs = one wave.
// Smem (halves): Qs[256][72] | K 3x[64][72] | V 3x[64][72] = 92160 B.
// ---------------------------------------------------------------------------
#define APH 72
#define ATTN_SMEM ((256*APH + 3*64*APH + 3*64*APH) * 2)

__global__ __launch_bounds__(256, 1)
void attn_tc_kernel()
{
    extern __shared__ __align__(16) __half asm_h[];
    __half* Qs  = asm_h;                     // [256][72]
    __half* Kst = asm_h + 256 * APH;         // 3 x [64][72]
    __half* Vst = Kst + 3 * 64 * APH;        // 3 x [64][72]
    unsigned K_u = (unsigned)__cvta_generic_to_shared(Kst);
    unsigned V_u = (unsigned)__cvta_generic_to_shared(Vst);

    int tid = threadIdx.x;
    int w = tid >> 5, lane = tid & 31;
    int grp = lane >> 2, qid = lane & 3;
    int wm = w << 4;
    int bh = blockIdx.y;
    int b = bh >> 4, h = bh & 15;
    int q0 = blockIdx.x << 8;                // 256 q-rows per CTA

    int lane15   = lane & 15;
    int acolsel  = (lane >> 4) << 3;
    int b_rowoff = (lane & 7) + ((lane >> 4) << 3);
    int bcolsel  = ((lane >> 3) & 1) << 3;

    const __half* qptr  = g_qh + ((size_t)bh * NS + q0) * HD;
    const __half* kptr  = g_kh + (size_t)bh * NS * HD;
    const __half* vTptr = g_vTh + (size_t)bh * HD * NS;
    // mask row pointers for the 4 q-rows this thread reduces
    const unsigned* mbp[2][2];
    mbp[0][0] = g_mb + (size_t)(b * NS + q0 + wm + grp) * 64;
    mbp[0][1] = mbp[0][0] + 8 * 64;
    mbp[1][0] = g_mb + (size_t)(b * NS + q0 + 128 + wm + grp) * 64;
    mbp[1][1] = mbp[1][0] + 8 * 64;

    // Q tile: 2048 16B chunks, 8/thread
    #pragma unroll
    for (int i = 0; i < 8; i++) {
        int cc = tid + (i << 8);
        int row = cc >> 3, seg = cc & 7;
        *(uint4*)&Qs[row * APH + seg * 8] = *(const uint4*)(qptr + row * HD + seg * 8);
    }

    int crow = tid >> 3, cseg = tid & 7;
    auto issueKV = [&](int t, int st) {
        int k0 = t << 6;
        #pragma unroll
        for (int i = 0; i < 2; i++) {
            int row = crow + i * 32;
            CP16(K_u + ((st * 64 + row) * APH + cseg * 8) * 2,
                 kptr + (size_t)(k0 + row) * HD + cseg * 8);
            CP16(V_u + ((st * 64 + row) * APH + cseg * 8) * 2,
                 vTptr + (size_t)row * NS + k0 + cseg * 8);
        }
    };

    issueKV(0, 0); CP_COMMIT();
    issueKV(1, 1); CP_COMMIT();

    float o[2][8][4];
    float mA[2][2], lA[2][2];
    #pragma unroll
    for (int hh = 0; hh < 2; hh++) {
        mA[hh][0] = -3.0e38f; mA[hh][1] = -3.0e38f;
        lA[hh][0] = 0.f; lA[hh][1] = 0.f;
        #pragma unroll
        for (int nt = 0; nt < 8; nt++)
            #pragma unroll
            for (int r = 0; r < 4; r++) o[hh][nt][r] = 0.f;
    }

    const int NT = NS / 64;   // 32
    int st = 0;
    for (int t = 0; t < NT; t++) {
        CP_WAIT1();
        __syncthreads();
        if (t + 2 < NT) {
            int nst = st + 2; if (nst >= 3) nst -= 3;
            issueKV(t + 2, nst);
        }
        CP_COMMIT();

        const __half* Ks = Kst + st * 64 * APH;
        const __half* Vs = Vst + st * 64 * APH;
        int kw = (t << 6) >> 5;   // mask word offset

        #pragma unroll
        for (int hh = 0; hh < 2; hh++) {
            // S = Q K^T for this q-half
            float sc[8][4];
            #pragma unroll
            for (int nt = 0; nt < 8; nt++)
                #pragma unroll
                for (int r = 0; r < 4; r++) sc[nt][r] = 0.f;

            const __half* Qhh = Qs + (hh * 128 + wm + lane15) * APH;
            #pragma unroll
            for (int kk = 0; kk < 4; kk++) {
                unsigned a0, a1, a2, a3;
                ldsm4(a0, a1, a2, a3, Qhh + kk * 16 + acolsel);
                #pragma unroll
                for (int ntp = 0; ntp < 4; ntp++) {
                    unsigned r0, r1, r2, r3;
                    ldsm4(r0, r1, r2, r3,
                          Ks + (ntp * 16 + b_rowoff) * APH + kk * 16 + bcolsel);
                    mma_f16(sc[ntp*2],   a0, a1, a2, a3, r0, r1);
                    mma_f16(sc[ntp*2+1], a0, a1, a2, a3, r2, r3);
                }
            }

            // mask (bare select; Q pre-scaled into exp2 domain)
            unsigned long long w0 = *(const unsigned long long*)(mbp[hh][0] + kw);
            unsigned long long w1 = *(const unsigned long long*)(mbp[hh][1] + kw);
            #pragma unroll
            for (int nt = 0; nt < 8; nt++) {
                int p = nt * 8 + (qid << 1);
                sc[nt][0] = ((w0 >> p)     & 1) ? sc[nt][0] : -1e30f;
                sc[nt][1] = ((w0 >> (p+1)) & 1) ? sc[nt][1] : -1e30f;
                sc[nt][2] = ((w1 >> p)     & 1) ? sc[nt][2] : -1e30f;
                sc[nt][3] = ((w1 >> (p+1)) & 1) ? sc[nt][3] : -1e30f;
            }

            float mx0 = -3.0e38f, mx1 = -3.0e38f;
            #pragma unroll
            for (int nt = 0; nt < 8; nt++) {
                mx0 = fmaxf(mx0, fmaxf(sc[nt][0], sc[nt][1]));
                mx1 = fmaxf(mx1, fmaxf(sc[nt][2], sc[nt][3]));
            }
            mx0 = fmaxf(mx0, __shfl_xor_sync(0xffffffffu, mx0, 1));
            mx0 = fmaxf(mx0, __shfl_xor_sync(0xffffffffu, mx0, 2));
            mx1 = fmaxf(mx1, __shfl_xor_sync(0xffffffffu, mx1, 1));
            mx1 = fmaxf(mx1, __shfl_xor_sync(0xffffffffu, mx1, 2));

            float m0 = mA[hh][0], m1 = mA[hh][1];
            float mn0 = fmaxf(m0, mx0), mn1 = fmaxf(m1, mx1);
            bool maxup = (mn0 > m0) || (mn1 > m1);
            unsigned anyup = __ballot_sync(0xffffffffu, maxup);

            unsigned pfrag[8][2];
            float ps0 = 0.f, ps1 = 0.f;
            #pragma unroll
            for (int nt = 0; nt < 8; nt++) {
                __half2 e0 = h2exp2(__floats2half2_rn(sc[nt][0] - mn0, sc[nt][1] - mn0));
                __half2 e1 = h2exp2(__floats2half2_rn(sc[nt][2] - mn1, sc[nt][3] - mn1));
                pfrag[nt][0] = *(unsigned*)&e0;
                pfrag[nt][1] = *(unsigned*)&e1;
                float2 f0 = __half22float2(e0);
                float2 f1 = __half22float2(e1);
                ps0 += f0.x + f0.y;
                ps1 += f1.x + f1.y;
            }
            ps0 += __shfl_xor_sync(0xffffffffu, ps0, 1);
            ps0 += __shfl_xor_sync(0xffffffffu, ps0, 2);
            ps1 += __shfl_xor_sync(0xffffffffu, ps1, 1);
            ps1 += __shfl_xor_sync(0xffffffffu, ps1, 2);

            if (anyup) {
                float corr0 = fex2(m0 - mn0), corr1 = fex2(m1 - mn1);
                mA[hh][0] = mn0; mA[hh][1] = mn1;
                lA[hh][0] = lA[hh][0] * corr0 + ps0;
                lA[hh][1] = lA[hh][1] * corr1 + ps1;
                #pragma unroll
                for (int nt = 0; nt < 8; nt++) {
                    o[hh][nt][0] *= corr0; o[hh][nt][1] *= corr0;
                    o[hh][nt][2] *= corr1; o[hh][nt][3] *= corr1;
                }
            } else {
                lA[hh][0] += ps0;
                lA[hh][1] += ps1;
            }

            #pragma unroll
            for (int kk = 0; kk < 4; kk++) {
                unsigned a0 = pfrag[2*kk][0];
                unsigned a1 = pfrag[2*kk][1];
                unsigned a2 = pfrag[2*kk+1][0];
                unsigned a3 = pfrag[2*kk+1][1];
                #pragma unroll
                for (int ntp = 0; ntp < 4; ntp++) {
                    unsigned r0, r1, r2, r3;
                    ldsm4(r0, r1, r2, r3,
                          Vs + (ntp * 16 + b_rowoff) * APH + kk * 16 + bcolsel);
                    mma_f16(o[hh][ntp*2],   a0, a1, a2, a3, r0, r1);
                    mma_f16(o[hh][ntp*2+1], a0, a1, a2, a3, r2, r3);
                }
            }
        }
        st++; if (st >= 3) st = 0;
    }

    // epilogue
    #pragma unroll
    for (int hh = 0; hh < 2; hh++) {
        float inv0 = 1.0f / lA[hh][0], inv1 = 1.0f / lA[hh][1];
        int r0 = q0 + hh * 128 + wm + grp, r1 = r0 + 8;
        #pragma unroll
        for (int nt = 0; nt < 8; nt++) {
            int col = h * HD + nt * 8 + (qid << 1);
            *(unsigned*)&g_ah[((size_t)b * NS + r0) * NDIM + col] =
                packh2(o[hh][nt][0] * inv0, o[hh][nt][1] * inv0);
            *(unsigned*)&g_ah[((size_t)b * NS + r1) * NDIM + col] =
                packh2(o[hh][nt][2] * inv1, o[hh][nt][3] * inv1);
        }
    }
}

// ---------------------------------------------------------------------------
extern "C" void kernel_launch(void* const* d_in, const int* in_sizes, int n_in,
                              void* d_out, int out_size) {
    const float* query = (const float*)d_in[0];
    const float* key   = (const float*)d_in[1];
    const float* value = (const float*)d_in[2];
    const int*   mask  = (const int*)d_in[3];
    const float* Wq = (const float*)d_in[4];
    const float* bq = (const float*)d_in[5];
    const float* Wk = (const float*)d_in[6];
    const float* bk = (const float*)d_in[7];
    const float* Wv = (const float*)d_in[8];
    const float* bv = (const float*)d_in[9];
    const float* Wo = (const float*)d_in[10];
    const float* bo = (const float*)d_in[11];

    float* out  = (float*)d_out;                 // [B,S,1024]
    float* outK = out + OUT_ELEMS;               // [B,H,S,64] (post-RoPE k)
    float* outV = out + 2 * (size_t)OUT_ELEMS;   // [B,H,S,64] (v)

    __half* g_inh_p; cudaGetSymbolAddress((void**)&g_inh_p, g_inh);
    __half* g_wh_p;  cudaGetSymbolAddress((void**)&g_wh_p, g_wh);

    static int smem_set = 0;
    if (!smem_set) {
        cudaFuncSetAttribute(qkv_tc_kernel, cudaFuncAttributeMaxDynamicSharedMemorySize,
                             LIN_SMEM);
        cudaFuncSetAttribute(out_tc_kernel, cudaFuncAttributeMaxDynamicSharedMemorySize,
                             LIN_SMEM);
        cudaFuncSetAttribute(attn_tc_kernel, cudaFuncAttributeMaxDynamicSharedMemorySize,
                             ATTN_SMEM);
        smem_set = 1;
    }

    const int A4 = NM * NDIM / 4;
    const int W4 = NDIM * NDIM / 4;

    rope_table_kernel<<<(NS * 32 + 255) / 256, 256>>>();
    mask_bits_kernel<<<(NB * NS * 32 + 255) / 256, 256>>>(mask);

    dim3 wgrid4(W4 / 1024, 4);
    f2h_multi_kernel<<<wgrid4, 256>>>(Wq, Wk, Wv, Wo, g_wh_p, W4);
    dim3 igrid3(A4 / 1024, 3);
    f2h_multi_kernel<<<igrid3, 256>>>(query, key, value, value, g_inh_p, A4);

    dim3 qkvgrid(NDIM / 256, NM / 128, 3);   // (4, 32, 3) = 384 CTAs
    qkv_tc_kernel<<<qkvgrid, 256, LIN_SMEM>>>(bq, bk, bv, outK, outV);

    dim3 agrid(NS / 256, NB * NH);           // (8, 32) = 256 CTAs
    attn_tc_kernel<<<agrid, 256, ATTN_SMEM>>>();

    dim3 ogrid(NDIM / 256, NM / 128);        // (4, 32)
    out_tc_kernel<<<ogrid, 256, LIN_SMEM>>>(bo, out);
}